// round 14
// baseline (speedup 1.0000x reference)
#include <cuda_runtime.h>
#include <cstdint>

#define BATCH   32
#define LPTS    8192
#define MSEL    2048
#define CSIZE   4                    // CTAs per batch (cluster)
#define NTHR    256
#define NWARP   (NTHR / 32)          // 8 warps per CTA
#define NAGENT  (CSIZE * NWARP)      // 32 warp-agents per batch
#define APTS    (LPTS / NAGENT)      // 256 points per agent
#define PPT     (APTS / 32)          // 8 points per lane
#define NPAIR   (PPT / 2)            // 4 packed pairs
#define CO_FLOATS (BATCH * MSEL * 3) // coords_out region size (floats)

typedef unsigned long long ull;

// ---- Blackwell packed f32x2 helpers (per-lane rn rounding == scalar) ------
__device__ __forceinline__ ull pk2(float lo, float hi) {
    ull r; asm("mov.b64 %0, {%1,%2};" : "=l"(r) : "f"(lo), "f"(hi)); return r;
}
__device__ __forceinline__ void upk2(ull v, float& lo, float& hi) {
    asm("mov.b64 {%0,%1}, %2;" : "=f"(lo), "=f"(hi) : "l"(v));
}
__device__ __forceinline__ ull add2(ull a, ull b) {
    ull r; asm("add.rn.f32x2 %0, %1, %2;" : "=l"(r) : "l"(a), "l"(b)); return r;
}
__device__ __forceinline__ ull mul2(ull a, ull b) {
    ull r; asm("mul.rn.f32x2 %0, %1, %2;" : "=l"(r) : "l"(a), "l"(b)); return r;
}
__device__ __forceinline__ ull fma2(ull a, ull b, ull c) {
    ull r; asm("fma.rn.f32x2 %0, %1, %2, %3;" : "=l"(r) : "l"(a), "l"(b), "l"(c)); return r;
}
__device__ __forceinline__ unsigned smem_u32(const void* p) {
    unsigned a;
    asm("{ .reg .u64 t; cvta.to.shared.u64 t, %1; cvt.u32.u64 %0, t; }"
        : "=r"(a) : "l"(p));
    return a;
}
__device__ __forceinline__ unsigned ctarank() {
    unsigned r; asm("mov.u32 %0, %%cluster_ctarank;" : "=r"(r)); return r;
}
__device__ __forceinline__ unsigned mapa_u32(unsigned local_addr, unsigned rank) {
    unsigned r;
    asm("mapa.shared::cluster.u32 %0, %1, %2;" : "=r"(r) : "r"(local_addr), "r"(rank));
    return r;
}

// ---------------------------------------------------------------------------
// Fused FPS + gather: 4-CTA cluster per batch; 32 warp-agents own 256 points
// each in packed f32x2 registers. Per iteration (no mbarrier, no barrier):
//   compute -> warp REDUX key -> lanes 0..3 DSMEM-store 64-bit key into all
//   4 CTAs' slot[parity][agent] -> copier STG (age-2 buffered row; fills the
//   poll-idle window) -> CONVERGED poll of own 32 slots (__all_sync per
//   attempt; divergent spin measured 2.4x slower, R10) -> REDUX global
//   argmax -> winner's packed negated coords via 3 uniform LDS.64 from
//   f-INDEXED pre-packed planes (no index arithmetic, no packing movs on the
//   critical path) -> copier LDG of winner's feature row (STG'd at it+2).
// Key = (dist_bits<<32) | ((8191-idx)<<3) | (it&7); the coord planes are
// permuted by f = 8191-idx so the key's low field indexes them directly.
// Tag+data share one word (per-location coherence suffices); parity-2 slot
// reuse is race-free via the it -> it+1 data dependency.
// Distance numerics BITWISE identical to reference lowering (validated R6):
//   d = fma(dz,dz, fma(dx,dx, fl(dy*dy))),  dx = c + (-l) [planes hold -l]
// Tie-break = lowest global index at every level (exact jnp.argmax).
// ---------------------------------------------------------------------------
__global__ void __launch_bounds__(NTHR, 1) __cluster_dims__(CSIZE, 1, 1)
fps_kernel(const float* __restrict__ coords,
           const float* __restrict__ feats,
           float* __restrict__ out)
{
    // Three permuted planes of packed negated coords: 3 x 8192 x u64 = 192KB.
    extern __shared__ ull s_pk[];
    ull* const s_x = s_pk;
    ull* const s_y = s_pk + LPTS;
    ull* const s_z = s_pk + 2 * LPTS;
    __shared__ ull slots[2][NAGENT];      // 2 parities x 32 agents = 512B

    const int      b     = blockIdx.x >> 2;
    const unsigned rank  = ctarank();
    const int      t     = threadIdx.x;
    const int      lane  = t & 31;
    const int      wid   = t >> 5;
    const int      agent = (int)rank * NWARP + wid;    // 0..31
    const int      base  = agent * APTS;               // global point base
    const float* __restrict__ cb = coords + (size_t)b * LPTS * 3;
    const float* __restrict__ fb = feats  + (size_t)b * LPTS * 128;

    // Zero slots (tag 0 != first tag 1) and fill the permuted coord planes:
    // plane slot f holds (-c,-c) of point idx = 8191-f.
    for (int i = t; i < 2 * NAGENT; i += NTHR) ((ull*)slots)[i] = 0ull;
    for (int i = t; i < LPTS; i += NTHR) {
        const float x = cb[i * 3 + 0];
        const float y = cb[i * 3 + 1];
        const float z = cb[i * 3 + 2];
        const int   f = (LPTS - 1) - i;
        s_x[f] = pk2(-x, -x);
        s_y[f] = pk2(-y, -y);
        s_z[f] = pk2(-z, -z);
    }
    __syncthreads();
    // All peers' slots must be zeroed before any remote store can land.
    asm volatile("barrier.cluster.arrive.aligned;" ::: "memory");
    asm volatile("barrier.cluster.wait.aligned;"   ::: "memory");

    // Precompute DSMEM addresses (mapa hoisted out of the loop).
    const unsigned s0 = smem_u32(&slots[0][agent]);
    const unsigned s1 = smem_u32(&slots[1][agent]);
    unsigned dst0 = 0, dst1 = 0;
    if (lane < CSIZE) {
        dst0 = mapa_u32(s0, (unsigned)lane);
        dst1 = mapa_u32(s1, (unsigned)lane);
    }
    const unsigned poll0 = smem_u32(&slots[0][lane]);
    const unsigned poll1 = smem_u32(&slots[1][lane]);

    // Load this agent's 256 points: lane p-index = base + lane + k*32.
    ull cx[NPAIR], cy[NPAIR], cz[NPAIR];
    float md[PPT];
#pragma unroll
    for (int q = 0; q < NPAIR; q++) {
        const int p0 = base + lane + (2 * q) * 32;
        const int p1 = p0 + 32;
        cx[q] = pk2(cb[p0 * 3 + 0], cb[p1 * 3 + 0]);
        cy[q] = pk2(cb[p0 * 3 + 1], cb[p1 * 3 + 1]);
        cz[q] = pk2(cb[p0 * 3 + 2], cb[p1 * 3 + 2]);
        md[2 * q]     = __int_as_float(0x7f800000);
        md[2 * q + 1] = __int_as_float(0x7f800000);
    }

    // Winner state: packed (-l,-l) pairs. Start = point 0 -> f = 8191.
    ull nlx = s_x[LPTS - 1];
    ull nly = s_y[LPTS - 1];
    ull nlz = s_z[LPTS - 1];

    // Copier pipeline (age 2): LDG at iter j (agent == j&31), STG at j+2.
    float4 fbuf = make_float4(0.f, 0.f, 0.f, 0.f);
    float  bx = 0.f, by = 0.f, bz = 0.f;
    int    brow = -1;                          // -1 = nothing buffered
    if (agent == 0) {
        fbuf = ((const float4*)fb)[lane];      // feature row of point 0
        bx = cb[0]; by = cb[1]; bz = cb[2];    // exact original coords
        brow = 0;
    }

    for (int it = 1; it < MSEL; it++) {
        const int      p   = it & 1;
        const unsigned tag = (unsigned)it & 7u;

        float    bv = -1.0f;                   // distances are >= 0
        unsigned bi = 0xffffffffu;

#pragma unroll
        for (int q = 0; q < NPAIR; q++) {
            const ull dx = add2(cx[q], nlx);   // c + (-l) == c - l exactly
            const ull dy = add2(cy[q], nly);
            const ull dz = add2(cz[q], nlz);
            ull dd = mul2(dy, dy);             // fl(dy*dy) rounded alone
            dd = fma2(dx, dx, dd);
            dd = fma2(dz, dz, dd);
            float d0, d1; upk2(dd, d0, d1);
            const float m0 = fminf(md[2 * q],     d0);
            const float m1 = fminf(md[2 * q + 1], d1);
            md[2 * q]     = m0;
            md[2 * q + 1] = m1;
            // ascending global idx + strict '>' => lowest index on ties
            if (m0 > bv) { bv = m0; bi = (unsigned)(base + lane + (2 * q) * 32); }
            if (m1 > bv) { bv = m1; bi = (unsigned)(base + lane + (2 * q) * 32 + 32); }
        }

        // Warp argmax (bits of non-negative floats are order-isomorphic).
        const unsigned vb   = __float_as_uint(bv);
        const unsigned wmax = __reduce_max_sync(0xffffffffu, vb);
        const unsigned wcnd = (vb == wmax) ? bi : 0xffffffffu;
        const unsigned wmin = __reduce_min_sync(0xffffffffu, wcnd);

        // Ship this agent's key to all 4 CTAs (lanes 0..3, one rank each).
        const ull key = ((ull)wmax << 32)
                      | ((ull)((8191u - wmin) & 0x1fffu) << 3)
                      | (ull)tag;
        if (lane < CSIZE) {
            const unsigned dst = p ? dst1 : dst0;
            asm volatile("st.relaxed.cluster.shared::cluster.u64 [%0], %1;"
                         :: "r"(dst), "l"(key) : "memory");
        }

        // Copier STG in the poll-idle window: data is from iteration it-2
        // (independent of this iteration's winner; age ~1300 cyc >> DRAM).
        if (agent == ((it - 2) & 31) && brow >= 0) {
            const int row = b * MSEL + brow;
            ((float4*)(out + CO_FLOATS + (size_t)row * 128))[lane] = fbuf;
            if (lane == 0) {
                out[(size_t)row * 3 + 0] = bx;
                out[(size_t)row * 3 + 1] = by;
                out[(size_t)row * 3 + 2] = bz;
            }
            brow = -1;
        }

        // Poll OWN smem: lane l watches slot[p][l]; spin until all 32 fresh.
        // MUST stay warp-converged (__all_sync per attempt) -- R10 lesson.
        const unsigned pa = p ? poll1 : poll0;
        ull k;
        bool ok;
        do {
            asm volatile("ld.volatile.shared.u64 %0, [%1];" : "=l"(k) : "r"(pa));
            ok = (((unsigned)k & 7u) == tag);
        } while (!__all_sync(0xffffffffu, ok));

        // Global argmax over the 32 agent keys:
        // max dist bits, then max (8191-idx) field = lowest index (tags equal).
        const unsigned hi   = (unsigned)(k >> 32);
        const unsigned hmax = __reduce_max_sync(0xffffffffu, hi);
        const unsigned cl   = (hi == hmax) ? (unsigned)k : 0u;
        const unsigned cmax = __reduce_max_sync(0xffffffffu, cl);
        const unsigned f    = (cmax >> 3) & 0x1fffu;   // = 8191 - gidx

        // Winner's packed negated coords: 3 uniform broadcast LDS.64 straight
        // off the f field -- no index arithmetic, no packing movs.
        nlx = s_x[f];
        nly = s_y[f];
        nlz = s_z[f];

        // Copier LDG: rotating owner buffers this winner's feature row.
        if (agent == (it & 31)) {
            const unsigned gidx = 8191u - f;
            fbuf = ((const float4*)(fb + (size_t)gidx * 128))[lane];
            if (lane == 0) {
                const float* c = cb + (size_t)gidx * 3;  // 2-iter slack
                bx = c[0]; by = c[1]; bz = c[2];
            }
            brow = it;
        }
    }

    // Drain: rows loaded at it = MSEL-2 and MSEL-1 are still buffered.
    if (brow >= 0) {
        const int row = b * MSEL + brow;
        ((float4*)(out + CO_FLOATS + (size_t)row * 128))[lane] = fbuf;
        if (lane == 0) {
            out[(size_t)row * 3 + 0] = bx;
            out[(size_t)row * 3 + 1] = by;
            out[(size_t)row * 3 + 2] = bz;
        }
    }

    // No CTA may exit while peers could still remote-write its smem.
    asm volatile("barrier.cluster.arrive.aligned;" ::: "memory");
    asm volatile("barrier.cluster.wait.aligned;"   ::: "memory");
}

extern "C" void kernel_launch(void* const* d_in, const int* in_sizes, int n_in,
                              void* d_out, int out_size)
{
    const float* coords = (const float*)d_in[0];   // [32, 8192, 3]
    const float* feats  = (const float*)d_in[1];   // [32, 8192, 128]
    float* out = (float*)d_out;

    const int smem = 3 * LPTS * sizeof(ull);       // 192KB packed coord planes
    cudaFuncSetAttribute(fps_kernel,
                         cudaFuncAttributeMaxDynamicSharedMemorySize, smem);
    fps_kernel<<<BATCH * CSIZE, NTHR, smem>>>(coords, feats, out);
}

// round 15
// speedup vs baseline: 1.0426x; 1.0426x over previous
#include <cuda_runtime.h>
#include <cstdint>

#define BATCH   32
#define LPTS    8192
#define MSEL    2048
#define CSIZE   4                    // CTAs per batch (cluster)
#define NTHR    256
#define NWARP   (NTHR / 32)          // 8 warps per CTA
#define NAGENT  (CSIZE * NWARP)      // 32 warp-agents per batch
#define APTS    (LPTS / NAGENT)      // 256 points per agent
#define PPT     (APTS / 32)          // 8 points per lane
#define NPAIR   (PPT / 2)            // 4 packed pairs
#define CO_FLOATS (BATCH * MSEL * 3) // coords_out region size (floats)

typedef unsigned long long ull;

// ---- Blackwell packed f32x2 helpers (per-lane rn rounding == scalar) ------
__device__ __forceinline__ ull pk2(float lo, float hi) {
    ull r; asm("mov.b64 %0, {%1,%2};" : "=l"(r) : "f"(lo), "f"(hi)); return r;
}
__device__ __forceinline__ void upk2(ull v, float& lo, float& hi) {
    asm("mov.b64 {%0,%1}, %2;" : "=f"(lo), "=f"(hi) : "l"(v));
}
__device__ __forceinline__ ull add2(ull a, ull b) {
    ull r; asm("add.rn.f32x2 %0, %1, %2;" : "=l"(r) : "l"(a), "l"(b)); return r;
}
__device__ __forceinline__ ull mul2(ull a, ull b) {
    ull r; asm("mul.rn.f32x2 %0, %1, %2;" : "=l"(r) : "l"(a), "l"(b)); return r;
}
__device__ __forceinline__ ull fma2(ull a, ull b, ull c) {
    ull r; asm("fma.rn.f32x2 %0, %1, %2, %3;" : "=l"(r) : "l"(a), "l"(b), "l"(c)); return r;
}
__device__ __forceinline__ unsigned smem_u32(const void* p) {
    unsigned a;
    asm("{ .reg .u64 t; cvta.to.shared.u64 t, %1; cvt.u32.u64 %0, t; }"
        : "=r"(a) : "l"(p));
    return a;
}
__device__ __forceinline__ unsigned ctarank() {
    unsigned r; asm("mov.u32 %0, %%cluster_ctarank;" : "=r"(r)); return r;
}
__device__ __forceinline__ unsigned mapa_u32(unsigned local_addr, unsigned rank) {
    unsigned r;
    asm("mapa.shared::cluster.u32 %0, %1, %2;" : "=r"(r) : "r"(local_addr), "r"(rank));
    return r;
}

// ---------------------------------------------------------------------------
// Fused FPS + gather: 4-CTA cluster per batch; 32 warp-agents own 256 points
// each in packed f32x2 registers. Per iteration (no mbarrier, no barrier):
//   compute -> warp REDUX key -> lanes 0..3 DSMEM-store 64-bit key into all
//   4 CTAs' slot[parity][agent] -> copier STG (age-2 buffered row; fills the
//   poll-idle window, data is 2 iterations old so no scoreboard stall) ->
//   CONVERGED poll of own 32 slots (__all_sync per attempt; divergent spin
//   measured 2.4x slower, R10) -> REDUX global argmax -> winner coords via
//   ONE uniform LDS.128 from a pre-negated float4 smem table -> copier LDG
//   of this winner's feature row (STG'd at it+2).
// Key = (dist_bits<<32) | ((8191-idx)<<3) | (it&7): tag+data share one word
// (per-location coherence suffices); parity-2 slot reuse is race-free via
// the it -> it+1 data dependency.
// Distance numerics BITWISE identical to reference lowering (validated R6):
//   d = fma(dz,dz, fma(dx,dx, fl(dy*dy))),  dx = c + (-l)  [smem holds -l]
// Tie-break = lowest global index at every level (exact jnp.argmax).
// ---------------------------------------------------------------------------
__global__ void __launch_bounds__(NTHR, 1) __cluster_dims__(CSIZE, 1, 1)
fps_kernel(const float* __restrict__ coords,
           const float* __restrict__ feats,
           float* __restrict__ out)
{
    extern __shared__ float4 s_neg[];     // 8192 x (-x,-y,-z,0) = 128KB
    __shared__ ull slots[2][NAGENT];      // 2 parities x 32 agents = 512B

    const int      b     = blockIdx.x >> 2;
    const unsigned rank  = ctarank();
    const int      t     = threadIdx.x;
    const int      lane  = t & 31;
    const int      wid   = t >> 5;
    const int      agent = (int)rank * NWARP + wid;    // 0..31
    const int      base  = agent * APTS;               // global point base
    const float* __restrict__ cb = coords + (size_t)b * LPTS * 3;
    const float* __restrict__ fb = feats  + (size_t)b * LPTS * 128;

    // Zero slots (tag 0 != first tag 1) and fill the negated coord table.
    for (int i = t; i < 2 * NAGENT; i += NTHR) ((ull*)slots)[i] = 0ull;
    for (int i = t; i < LPTS; i += NTHR) {
        const float x = cb[i * 3 + 0];
        const float y = cb[i * 3 + 1];
        const float z = cb[i * 3 + 2];
        s_neg[i] = make_float4(-x, -y, -z, 0.0f);
    }
    __syncthreads();
    // All peers' slots must be zeroed before any remote store can land.
    asm volatile("barrier.cluster.arrive.aligned;" ::: "memory");
    asm volatile("barrier.cluster.wait.aligned;"   ::: "memory");

    // Precompute DSMEM addresses (mapa hoisted out of the loop).
    const unsigned s0 = smem_u32(&slots[0][agent]);
    const unsigned s1 = smem_u32(&slots[1][agent]);
    unsigned dst0 = 0, dst1 = 0;
    if (lane < CSIZE) {
        dst0 = mapa_u32(s0, (unsigned)lane);
        dst1 = mapa_u32(s1, (unsigned)lane);
    }
    const unsigned poll0 = smem_u32(&slots[0][lane]);
    const unsigned poll1 = smem_u32(&slots[1][lane]);

    // Load this agent's 256 points: lane p-index = base + lane + k*32.
    ull cx[NPAIR], cy[NPAIR], cz[NPAIR];
    float md[PPT];
#pragma unroll
    for (int q = 0; q < NPAIR; q++) {
        const int p0 = base + lane + (2 * q) * 32;
        const int p1 = p0 + 32;
        cx[q] = pk2(cb[p0 * 3 + 0], cb[p1 * 3 + 0]);
        cy[q] = pk2(cb[p0 * 3 + 1], cb[p1 * 3 + 1]);
        cz[q] = pk2(cb[p0 * 3 + 2], cb[p1 * 3 + 2]);
        md[2 * q]     = __int_as_float(0x7f800000);
        md[2 * q + 1] = __int_as_float(0x7f800000);
    }

    // Winner state: w = NEGATED coords of the last selected point.
    float4 w = s_neg[0];                       // point 0 (deterministic start)

    // Copier pipeline (age 2): LDG at iter j (agent == j&31), STG at j+2.
    float4 fbuf = make_float4(0.f, 0.f, 0.f, 0.f);
    float  bx = 0.f, by = 0.f, bz = 0.f;
    int    brow = -1;                          // -1 = nothing buffered
    if (agent == 0) {
        fbuf = ((const float4*)fb)[lane];      // feature row of point 0
        bx = -w.x; by = -w.y; bz = -w.z;       // positive coords (bitwise)
        brow = 0;
    }

    for (int it = 1; it < MSEL; it++) {
        const int      p   = it & 1;
        const unsigned tag = (unsigned)it & 7u;
        const ull nlx = pk2(w.x, w.x);         // already negated
        const ull nly = pk2(w.y, w.y);
        const ull nlz = pk2(w.z, w.z);

        float    bv = -1.0f;                   // distances are >= 0
        unsigned bi = 0xffffffffu;

#pragma unroll
        for (int q = 0; q < NPAIR; q++) {
            const ull dx = add2(cx[q], nlx);   // c + (-l) == c - l exactly
            const ull dy = add2(cy[q], nly);
            const ull dz = add2(cz[q], nlz);
            ull dd = mul2(dy, dy);             // fl(dy*dy) rounded alone
            dd = fma2(dx, dx, dd);
            dd = fma2(dz, dz, dd);
            float d0, d1; upk2(dd, d0, d1);
            const float m0 = fminf(md[2 * q],     d0);
            const float m1 = fminf(md[2 * q + 1], d1);
            md[2 * q]     = m0;
            md[2 * q + 1] = m1;
            // ascending global idx + strict '>' => lowest index on ties
            if (m0 > bv) { bv = m0; bi = (unsigned)(base + lane + (2 * q) * 32); }
            if (m1 > bv) { bv = m1; bi = (unsigned)(base + lane + (2 * q) * 32 + 32); }
        }

        // Warp argmax (bits of non-negative floats are order-isomorphic).
        const unsigned vb   = __float_as_uint(bv);
        const unsigned wmax = __reduce_max_sync(0xffffffffu, vb);
        const unsigned wcnd = (vb == wmax) ? bi : 0xffffffffu;
        const unsigned wmin = __reduce_min_sync(0xffffffffu, wcnd);

        // Ship this agent's key to all 4 CTAs (lanes 0..3, one rank each).
        const ull key = ((ull)wmax << 32)
                      | ((ull)((8191u - wmin) & 0x1fffu) << 3)
                      | (ull)tag;
        if (lane < CSIZE) {
            const unsigned dst = p ? dst1 : dst0;
            asm volatile("st.relaxed.cluster.shared::cluster.u64 [%0], %1;"
                         :: "r"(dst), "l"(key) : "memory");
        }

        // Copier STG in the poll-idle window: data is from iteration it-2
        // (independent of this iteration's winner; age ~1300 cyc >> DRAM).
        if (agent == ((it - 2) & 31) && brow >= 0) {
            const int row = b * MSEL + brow;
            ((float4*)(out + CO_FLOATS + (size_t)row * 128))[lane] = fbuf;
            if (lane == 0) {
                out[(size_t)row * 3 + 0] = bx;
                out[(size_t)row * 3 + 1] = by;
                out[(size_t)row * 3 + 2] = bz;
            }
            brow = -1;
        }

        // Poll OWN smem: lane l watches slot[p][l]; spin until all 32 fresh.
        // MUST stay warp-converged (__all_sync per attempt) -- R10 lesson.
        const unsigned pa = p ? poll1 : poll0;
        ull k;
        bool ok;
        do {
            asm volatile("ld.volatile.shared.u64 %0, [%1];" : "=l"(k) : "r"(pa));
            ok = (((unsigned)k & 7u) == tag);
        } while (!__all_sync(0xffffffffu, ok));

        // Global argmax over the 32 agent keys:
        // max dist bits, then max (8191-idx) field = lowest index (tags equal).
        const unsigned hi   = (unsigned)(k >> 32);
        const unsigned hmax = __reduce_max_sync(0xffffffffu, hi);
        const unsigned cl   = (hi == hmax) ? (unsigned)k : 0u;
        const unsigned cmax = __reduce_max_sync(0xffffffffu, cl);
        const unsigned gidx = 8191u - ((cmax >> 3) & 0x1fffu);

        // New winner's negated coords: one uniform LDS.128 (broadcast).
        w = s_neg[gidx];

        // Copier LDG: rotating owner buffers this winner's feature row.
        if (agent == (it & 31)) {
            fbuf = ((const float4*)(fb + (size_t)gidx * 128))[lane];
            bx = -w.x; by = -w.y; bz = -w.z;   // bitwise-exact positives
            brow = it;
        }
    }

    // Drain: rows loaded at it = MSEL-2 and MSEL-1 are still buffered.
    if (brow >= 0) {
        const int row = b * MSEL + brow;
        ((float4*)(out + CO_FLOATS + (size_t)row * 128))[lane] = fbuf;
        if (lane == 0) {
            out[(size_t)row * 3 + 0] = bx;
            out[(size_t)row * 3 + 1] = by;
            out[(size_t)row * 3 + 2] = bz;
        }
    }

    // No CTA may exit while peers could still remote-write its smem.
    asm volatile("barrier.cluster.arrive.aligned;" ::: "memory");
    asm volatile("barrier.cluster.wait.aligned;"   ::: "memory");
}

extern "C" void kernel_launch(void* const* d_in, const int* in_sizes, int n_in,
                              void* d_out, int out_size)
{
    const float* coords = (const float*)d_in[0];   // [32, 8192, 3]
    const float* feats  = (const float*)d_in[1];   // [32, 8192, 128]
    float* out = (float*)d_out;

    const int smem = LPTS * sizeof(float4);        // 128KB negated coord table
    cudaFuncSetAttribute(fps_kernel,
                         cudaFuncAttributeMaxDynamicSharedMemorySize, smem);
    fps_kernel<<<BATCH * CSIZE, NTHR, smem>>>(coords, feats, out);
}